// round 8
// baseline (speedup 1.0000x reference)
#include <cuda_runtime.h>
#include <math.h>

#define BB 8
#define SS 16
#define HH 16
#define DD 128
#define EE 2048
#define MM 128          // B*S rows
#define TCACHE 4096
#define NTILES 129      // 128 cache tiles of 32 keys + 1 new-key tile of 16

// ---------------- scratch (device globals) ----------------------------------
__device__ float g_q[MM * EE];     // (b,h,s,d): ((b*16+h)*16+s)*128+d
__device__ float g_ctx[MM * EE];   // (b,s,e) row-major

// ---------------- f32x2 helpers ---------------------------------------------
__device__ __forceinline__ void ffma2(unsigned long long& d,
                                      unsigned long long a,
                                      unsigned long long b) {
    asm("fma.rn.f32x2 %0, %1, %2, %0;" : "+l"(d) : "l"(a), "l"(b));
}
__device__ __forceinline__ void fmul2(unsigned long long& d,
                                      unsigned long long b) {
    asm("mul.rn.f32x2 %0, %0, %1;" : "+l"(d) : "l"(b));
}
__device__ __forceinline__ unsigned long long dup2(float x) {
    unsigned long long r;
    unsigned xi = __float_as_uint(x);
    asm("mov.b64 %0, {%1, %2};" : "=l"(r) : "r"(xi), "r"(xi));
    return r;
}
__device__ __forceinline__ float lo32(unsigned long long v) {
    return __uint_as_float((unsigned)(v & 0xffffffffull));
}
__device__ __forceinline__ float hi32(unsigned long long v) {
    return __uint_as_float((unsigned)(v >> 32));
}

// =============================================================================
// QKV GEMM: Y(128 x 2048) = X @ W^T + b.  BM=128, BN=64, BK=16, 256 threads,
// 8m x 4n per thread (m packed in f32x2 pairs). z selects Wq/Wk/Wv.
// Output layout (b,h,s,d): ((b*16+h)*16+s)*128+d  (m=b*16+s, f=h*128+d)
// =============================================================================
__global__ __launch_bounds__(256) void qkv_gemm(const float* __restrict__ emb,
                                                const float* __restrict__ Wq,
                                                const float* __restrict__ Wk,
                                                const float* __restrict__ Wv,
                                                const float* __restrict__ bq,
                                                const float* __restrict__ bk,
                                                const float* __restrict__ bv,
                                                float* __restrict__ kout,
                                                float* __restrict__ vout) {
    __shared__ __align__(16) float Xs[16 * 132];  // [k][m]
    __shared__ __align__(16) float Ws[16 * 68];   // [k][n]

    const float* W;
    const float* bias;
    float* o;
    if (blockIdx.z == 0) { W = Wq; bias = bq; o = g_q; }
    else if (blockIdx.z == 1) { W = Wk; bias = bk; o = kout; }
    else { W = Wv; bias = bv; o = vout; }

    int tid = threadIdx.x;
    int f0 = blockIdx.x * 64;
    int lrx = tid >> 1, lcx = (tid & 1) * 2;   // X: row lrx, k-cols [lcx*4, lcx*4+8)
    int lrw = tid >> 2, lcw = tid & 3;         // W: row lrw, k-cols [lcw*4, lcw*4+4)
    int mg = tid & 15, ng = tid >> 4;

    float4 xr0 = *reinterpret_cast<const float4*>(emb + (size_t)lrx * EE + lcx * 4);
    float4 xr1 = *reinterpret_cast<const float4*>(emb + (size_t)lrx * EE + lcx * 4 + 4);
    float4 wr  = *reinterpret_cast<const float4*>(W + (size_t)(f0 + lrw) * EE + lcw * 4);

    unsigned long long acc[4][4] = {};  // [mp][nn]

    for (int kt = 0; kt < EE; kt += 16) {
        __syncthreads();
        Xs[(lcx * 4 + 0) * 132 + lrx] = xr0.x;
        Xs[(lcx * 4 + 1) * 132 + lrx] = xr0.y;
        Xs[(lcx * 4 + 2) * 132 + lrx] = xr0.z;
        Xs[(lcx * 4 + 3) * 132 + lrx] = xr0.w;
        Xs[(lcx * 4 + 4) * 132 + lrx] = xr1.x;
        Xs[(lcx * 4 + 5) * 132 + lrx] = xr1.y;
        Xs[(lcx * 4 + 6) * 132 + lrx] = xr1.z;
        Xs[(lcx * 4 + 7) * 132 + lrx] = xr1.w;
        Ws[(lcw * 4 + 0) * 68 + lrw] = wr.x;
        Ws[(lcw * 4 + 1) * 68 + lrw] = wr.y;
        Ws[(lcw * 4 + 2) * 68 + lrw] = wr.z;
        Ws[(lcw * 4 + 3) * 68 + lrw] = wr.w;
        __syncthreads();
        if (kt + 16 < EE) {
            xr0 = *reinterpret_cast<const float4*>(emb + (size_t)lrx * EE + kt + 16 + lcx * 4);
            xr1 = *reinterpret_cast<const float4*>(emb + (size_t)lrx * EE + kt + 16 + lcx * 4 + 4);
            wr  = *reinterpret_cast<const float4*>(W + (size_t)(f0 + lrw) * EE + kt + 16 + lcw * 4);
        }
#pragma unroll
        for (int k = 0; k < 16; k++) {
            unsigned long long a[4];
#pragma unroll
            for (int mp = 0; mp < 4; mp++)
                a[mp] = *reinterpret_cast<const unsigned long long*>(
                    &Xs[k * 132 + 2 * mg + 32 * mp]);
#pragma unroll
            for (int nn = 0; nn < 4; nn++) {
                unsigned long long bv2 = dup2(Ws[k * 68 + ng * 4 + nn]);
#pragma unroll
                for (int mp = 0; mp < 4; mp++) ffma2(acc[mp][nn], a[mp], bv2);
            }
        }
    }

#pragma unroll
    for (int nn = 0; nn < 4; nn++) {
        int f = f0 + ng * 4 + nn;
        float bvv = bias[f];
        int h = f >> 7, d = f & 127;
#pragma unroll
        for (int mp = 0; mp < 4; mp++) {
            int m = 2 * mg + 32 * mp;          // even, so m and m+1 share b
            int b = m >> 4, s = m & 15;
            size_t base = (((size_t)(b * HH + h)) * SS + s) * DD + d;
            o[base]      = lo32(acc[mp][nn]) + bvv;
            o[base + DD] = hi32(acc[mp][nn]) + bvv;   // s+1
        }
    }
}

// =============================================================================
// Output GEMM: out(128 x 2048) = ctx @ Wo^T + bo. BM=64, BN=64, 128 threads,
// 8m x 4n per thread. grid (32, 2).
// =============================================================================
__global__ __launch_bounds__(128) void out_gemm(const float* __restrict__ Wo,
                                                const float* __restrict__ bo,
                                                float* __restrict__ out) {
    __shared__ __align__(16) float Xs[16 * 68];
    __shared__ __align__(16) float Ws[16 * 68];

    int tid = threadIdx.x;
    int m0 = blockIdx.y * 64;
    int f0 = blockIdx.x * 64;
    int lr = tid >> 1, lc = (tid & 1) * 2;  // both X and W: row lr, k-cols [lc*4, lc*4+8)
    int mg = tid & 7, ng = tid >> 3;

    const float* X = g_ctx;
    float4 xr0 = *reinterpret_cast<const float4*>(X + (size_t)(m0 + lr) * EE + lc * 4);
    float4 xr1 = *reinterpret_cast<const float4*>(X + (size_t)(m0 + lr) * EE + lc * 4 + 4);
    float4 wr0 = *reinterpret_cast<const float4*>(Wo + (size_t)(f0 + lr) * EE + lc * 4);
    float4 wr1 = *reinterpret_cast<const float4*>(Wo + (size_t)(f0 + lr) * EE + lc * 4 + 4);

    unsigned long long acc[4][4] = {};

    for (int kt = 0; kt < EE; kt += 16) {
        __syncthreads();
        Xs[(lc * 4 + 0) * 68 + lr] = xr0.x;
        Xs[(lc * 4 + 1) * 68 + lr] = xr0.y;
        Xs[(lc * 4 + 2) * 68 + lr] = xr0.z;
        Xs[(lc * 4 + 3) * 68 + lr] = xr0.w;
        Xs[(lc * 4 + 4) * 68 + lr] = xr1.x;
        Xs[(lc * 4 + 5) * 68 + lr] = xr1.y;
        Xs[(lc * 4 + 6) * 68 + lr] = xr1.z;
        Xs[(lc * 4 + 7) * 68 + lr] = xr1.w;
        Ws[(lc * 4 + 0) * 68 + lr] = wr0.x;
        Ws[(lc * 4 + 1) * 68 + lr] = wr0.y;
        Ws[(lc * 4 + 2) * 68 + lr] = wr0.z;
        Ws[(lc * 4 + 3) * 68 + lr] = wr0.w;
        Ws[(lc * 4 + 4) * 68 + lr] = wr1.x;
        Ws[(lc * 4 + 5) * 68 + lr] = wr1.y;
        Ws[(lc * 4 + 6) * 68 + lr] = wr1.z;
        Ws[(lc * 4 + 7) * 68 + lr] = wr1.w;
        __syncthreads();
        if (kt + 16 < EE) {
            xr0 = *reinterpret_cast<const float4*>(X + (size_t)(m0 + lr) * EE + kt + 16 + lc * 4);
            xr1 = *reinterpret_cast<const float4*>(X + (size_t)(m0 + lr) * EE + kt + 16 + lc * 4 + 4);
            wr0 = *reinterpret_cast<const float4*>(Wo + (size_t)(f0 + lr) * EE + kt + 16 + lc * 4);
            wr1 = *reinterpret_cast<const float4*>(Wo + (size_t)(f0 + lr) * EE + kt + 16 + lc * 4 + 4);
        }
#pragma unroll
        for (int k = 0; k < 16; k++) {
            unsigned long long a[4];
#pragma unroll
            for (int mp = 0; mp < 4; mp++)
                a[mp] = *reinterpret_cast<const unsigned long long*>(
                    &Xs[k * 68 + 2 * mg + 16 * mp]);
#pragma unroll
            for (int nn = 0; nn < 4; nn++) {
                unsigned long long bv2 = dup2(Ws[k * 68 + ng * 4 + nn]);
#pragma unroll
                for (int mp = 0; mp < 4; mp++) ffma2(acc[mp][nn], a[mp], bv2);
            }
        }
    }

#pragma unroll
    for (int nn = 0; nn < 4; nn++) {
        int f = f0 + ng * 4 + nn;
        float bvv = bo[f];
#pragma unroll
        for (int mp = 0; mp < 4; mp++) {
            int m = m0 + 2 * mg + 16 * mp;
            out[(size_t)m * EE + f]       = lo32(acc[mp][nn]) + bvv;
            out[(size_t)(m + 1) * EE + f] = hi32(acc[mp][nn]) + bvv;
        }
    }
}

// =============================================================================
// Fused flash attention, one CTA per (b,h), 256 threads, 32-key tiles.
// Q in registers. Score partials staged through a plane that aliases the
// V region. Register-prefetched K/V (software pipeline). 4 syncs per tile.
// =============================================================================
__global__ __launch_bounds__(256) void flash_kernel(const float* __restrict__ kc,
                                                    const float* __restrict__ vc,
                                                    const float* __restrict__ knew,
                                                    const float* __restrict__ vnew) {
    // SM[0:4224)    = Ks[j][132]
    // SM[4224:8448) = Vs[j][132]  (also Sp[dg][16][33] between scores and reduce)
    // SM[0:8448)    = FB[256][33] for the final o reduction
    __shared__ __align__(16) float SM[8448];
    __shared__ float Ss[16 * 34];
    __shared__ float m_s[16], l_s[16], c_s[16];

    float* Ks = SM;
    float* Vs = SM + 4224;
    float* SP = SM + 4224;
    float* FB = SM;

    int tid = threadIdx.x;
    int bh = blockIdx.x;

    // --- stage-A (scores) ids: q-group, key-group, d-eighth (=warp) ---------
    int qgA = tid & 3;          // 4 groups x 4 queries
    int kgA = (tid >> 2) & 7;   // keys j = kgA + 8*kk
    int dgA = tid >> 5;         // d in [dgA*16, dgA*16+16)

    // Q registers (tile-invariant)
    unsigned long long qreg[4][8];
    {
        const float* qb = g_q + (size_t)bh * (SS * DD);
#pragma unroll
        for (int qq = 0; qq < 4; qq++)
#pragma unroll
            for (int dp = 0; dp < 8; dp++)
                qreg[qq][dp] = *reinterpret_cast<const unsigned long long*>(
                    qb + (qgA * 4 + qq) * DD + dgA * 16 + 2 * dp);
    }

    // --- stage-C (PV) ids ----------------------------------------------------
    int dg2 = tid & 15;          // d-pairs dg2 + 16*r  -> d = 2*dg2 + 32*r
    int qg2 = (tid >> 4) & 3;    // 4 groups x 4 queries
    int ksl = tid >> 6;          // 4 key slices x 8 keys
    unsigned long long o2[4][4] = {};  // [qq][r]

    if (tid < 16) { m_s[tid] = -1e30f; l_s[tid] = 0.f; }

    // --- K/V tile loader ids -------------------------------------------------
    int jl = tid >> 3;           // row 0..31
    int cl = tid & 7;            // float4 cols cl, cl+8, cl+16, cl+24

    const float scale = 0.08838834764831845f;  // 1/sqrt(128)

    // preload tile 0 K into registers
    float4 kpre[4], vpre[4];
    {
        const float* ks0 = kc + ((size_t)bh * TCACHE) * DD;
#pragma unroll
        for (int t = 0; t < 4; t++)
            kpre[t] = *reinterpret_cast<const float4*>(ks0 + (size_t)jl * DD + cl * 4 + 32 * t);
    }

    for (int tile = 0; tile < NTILES; tile++) {
        int nj = (tile < 128) ? 32 : 16;
        bool on = jl < nj;

        // STS K (prefetched)
        if (on) {
#pragma unroll
            for (int t = 0; t < 4; t++)
                *reinterpret_cast<float4*>(&Ks[jl * 132 + cl * 4 + 32 * t]) = kpre[t];
        }
        __syncthreads();  // (a) K visible; all threads past previous PV

        // issue V prefetch for THIS tile (lands during scores)
        {
            const float* vsrc = (tile < 128)
                ? vc + ((size_t)bh * TCACHE + (size_t)tile * 32) * DD
                : vnew + (size_t)bh * (SS * DD);
            if (on) {
#pragma unroll
                for (int t = 0; t < 4; t++)
                    vpre[t] = *reinterpret_cast<const float4*>(
                        vsrc + (size_t)jl * DD + cl * 4 + 32 * t);
            }
        }

        // scores: acc[qq][kk] over this thread's 16 d's
        {
            unsigned long long acc[4][4] = {};
#pragma unroll
            for (int dp = 0; dp < 8; dp++) {
#pragma unroll
                for (int kk = 0; kk < 4; kk++) {
                    unsigned long long kv =
                        *reinterpret_cast<const unsigned long long*>(
                            &Ks[(kgA + 8 * kk) * 132 + dgA * 16 + 2 * dp]);
#pragma unroll
                    for (int qq = 0; qq < 4; qq++)
                        ffma2(acc[qq][kk], qreg[qq][dp], kv);
                }
            }
            // partial scores -> SP (aliases Vs; safe after sync (a))
#pragma unroll
            for (int qq = 0; qq < 4; qq++)
#pragma unroll
                for (int kk = 0; kk < 4; kk++)
                    SP[dgA * 528 + (qgA * 4 + qq) * 33 + (kgA + 8 * kk)] =
                        lo32(acc[qq][kk]) + hi32(acc[qq][kk]);
        }
        __syncthreads();  // (b) SP complete

        // reduce 8 d-partials -> Ss, apply scale + causal mask on last tile
        {
#pragma unroll
            for (int half = 0; half < 2; half++) {
                int pp = tid + 256 * half;
                int q = pp >> 5, k = pp & 31;
                float s = 0.f;
#pragma unroll
                for (int dg = 0; dg < 8; dg++) s += SP[dg * 528 + q * 33 + k];
                s *= scale;
                if (tile == 128 && k > q) s = -1e30f;  // masks k>=16 garbage too
                Ss[q * 34 + k] = s;
            }
        }
        __syncthreads();  // (c) Ss ready, SP consumed

        // STS V (over SP) + online softmax by 16 threads
        if (on) {
#pragma unroll
            for (int t = 0; t < 4; t++)
                *reinterpret_cast<float4*>(&Vs[jl * 132 + cl * 4 + 32 * t]) = vpre[t];
        }
        if (tid < 16) {
            float* row = Ss + tid * 34;
            float mold = m_s[tid];
            float mx = mold;
            for (int j = 0; j < nj; j++) mx = fmaxf(mx, row[j]);
            float c = __expf(mold - mx);
            float sum = 0.f;
            for (int j = 0; j < nj; j++) {
                float p = __expf(row[j] - mx);
                row[j] = p;
                sum += p;
            }
            m_s[tid] = mx;
            l_s[tid] = l_s[tid] * c + sum;
            c_s[tid] = c;
        }
        __syncthreads();  // (d) V + P + c ready

        // prefetch NEXT tile K (lands during PV)
        if (tile + 1 < NTILES) {
            int tn = tile + 1;
            int njn = (tn < 128) ? 32 : 16;
            const float* ksrc = (tn < 128)
                ? kc + ((size_t)bh * TCACHE + (size_t)tn * 32) * DD
                : knew + (size_t)bh * (SS * DD);
            if (jl < njn) {
#pragma unroll
                for (int t = 0; t < 4; t++)
                    kpre[t] = *reinterpret_cast<const float4*>(
                        ksrc + (size_t)jl * DD + cl * 4 + 32 * t);
            }
        }

        // PV: o = o*c + P @ V on this thread's key slice
        {
            unsigned long long cf[4];
#pragma unroll
            for (int qq = 0; qq < 4; qq++) cf[qq] = dup2(c_s[qg2 * 4 + qq]);
#pragma unroll
            for (int qq = 0; qq < 4; qq++)
#pragma unroll
                for (int r = 0; r < 4; r++) fmul2(o2[qq][r], cf[qq]);

#pragma unroll
            for (int jj = 0; jj < 8; jj++) {
                int j = ksl * 8 + jj;
                if (j < nj) {
                    unsigned long long pf[4];
#pragma unroll
                    for (int qq = 0; qq < 4; qq++)
                        pf[qq] = dup2(Ss[(qg2 * 4 + qq) * 34 + j]);
#pragma unroll
                    for (int r = 0; r < 4; r++) {
                        unsigned long long vv =
                            *reinterpret_cast<const unsigned long long*>(
                                &Vs[j * 132 + 2 * dg2 + 32 * r]);
#pragma unroll
                        for (int qq = 0; qq < 4; qq++) ffma2(o2[qq][r], pf[qq], vv);
                    }
                }
            }
        }
    }

    // final: reduce 4 key-slice partials through FB, normalize, write g_ctx
    __syncthreads();
    if (tid < 16) c_s[tid] = 1.f / l_s[tid];
#pragma unroll
    for (int qq = 0; qq < 4; qq++)
#pragma unroll
        for (int r = 0; r < 4; r++) {
            FB[tid * 33 + qq * 8 + r * 2]     = lo32(o2[qq][r]);
            FB[tid * 33 + qq * 8 + r * 2 + 1] = hi32(o2[qq][r]);
        }
    __syncthreads();
    if (tid < 64) {
        int b = bh >> 4, h = bh & 15;
#pragma unroll
        for (int i = 0; i < 32; i++) {
            float v = FB[tid * 33 + i] + FB[(tid + 64) * 33 + i] +
                      FB[(tid + 128) * 33 + i] + FB[(tid + 192) * 33 + i];
            int qq = i >> 3, r = (i >> 1) & 3, lh = i & 1;
            int q = qg2 * 4 + qq;
            int d = 2 * dg2 + 32 * r + lh;
            g_ctx[((size_t)(b * SS + q)) * EE + h * DD + d] = v * c_s[q];
        }
    }
}

// ---------------- launch -----------------------------------------------------
extern "C" void kernel_launch(void* const* d_in, const int* in_sizes, int n_in,
                              void* d_out, int out_size) {
    const float* emb = (const float*)d_in[0];
    const float* kc  = (const float*)d_in[1];
    const float* vc  = (const float*)d_in[2];
    const float* Wq  = (const float*)d_in[3];
    const float* bq  = (const float*)d_in[4];
    const float* Wk  = (const float*)d_in[5];
    const float* bk  = (const float*)d_in[6];
    const float* Wv  = (const float*)d_in[7];
    const float* bv  = (const float*)d_in[8];
    const float* Wo  = (const float*)d_in[9];
    const float* bo  = (const float*)d_in[10];

    float* out  = (float*)d_out;          // (8,16,2048)
    float* kout = out + MM * EE;          // k_new (8,16,16,128)
    float* vout = out + 2 * MM * EE;      // v_new (8,16,16,128)

    qkv_gemm<<<dim3(32, 1, 3), 256>>>(emb, Wq, Wk, Wv, bq, bk, bv, kout, vout);
    flash_kernel<<<128, 256>>>(kc, vc, kout, vout);
    out_gemm<<<dim3(32, 2, 1), 128>>>(Wo, bo, out);
}

// round 9
// speedup vs baseline: 1.1764x; 1.1764x over previous
#include <cuda_runtime.h>
#include <math.h>

#define BB 8
#define SS 16
#define HH 16
#define DD 128
#define EE 2048
#define MM 128          // B*S rows
#define TCACHE 4096
#define NTILES 129      // 128 cache tiles of 32 keys + 1 new-key tile of 16

// ---------------- scratch (device globals) ----------------------------------
__device__ float g_q[MM * EE];     // (b,h,s,d): ((b*16+h)*16+s)*128+d
__device__ float g_ctx[MM * EE];   // (b,s,e) row-major

// ---------------- f32x2 helpers ---------------------------------------------
__device__ __forceinline__ void ffma2(unsigned long long& d,
                                      unsigned long long a,
                                      unsigned long long b) {
    asm("fma.rn.f32x2 %0, %1, %2, %0;" : "+l"(d) : "l"(a), "l"(b));
}
__device__ __forceinline__ void fmul2(unsigned long long& d,
                                      unsigned long long b) {
    asm("mul.rn.f32x2 %0, %0, %1;" : "+l"(d) : "l"(b));
}
__device__ __forceinline__ unsigned long long dup2(float x) {
    unsigned long long r;
    unsigned xi = __float_as_uint(x);
    asm("mov.b64 %0, {%1, %2};" : "=l"(r) : "r"(xi), "r"(xi));
    return r;
}
__device__ __forceinline__ float lo32(unsigned long long v) {
    return __uint_as_float((unsigned)(v & 0xffffffffull));
}
__device__ __forceinline__ float hi32(unsigned long long v) {
    return __uint_as_float((unsigned)(v >> 32));
}

// =============================================================================
// GEMM body: Y(tile 64m x 32n) = X @ W^T + b.  BK=16, 128 threads.
// Thread tile: 4m (2 f32x2 pairs) x 4n. Register double-buffered glob loads.
// MODE 0: out[m*2048 + f]
// MODE 1: out[((b*16+h)*16+s)*128+d], b=m>>4, s=m&15, h=f>>7, d=f&127
// =============================================================================
template <int MODE>
__device__ __forceinline__ void gemm32_body(const float* __restrict__ X,
                                            const float* __restrict__ W,
                                            const float* __restrict__ bias,
                                            float* __restrict__ out) {
    __shared__ __align__(16) float Xs[16 * 66];  // [k][m] pad 66
    __shared__ __align__(16) float Ws[16 * 36];  // [k][n] pad 36

    int tid = threadIdx.x;
    int m0 = blockIdx.y * 64;
    int f0 = blockIdx.x * 32;
    int lrx = tid >> 1, lcx = (tid & 1) * 8;   // X: row lrx, k-cols [lcx, lcx+8)
    int lrw = tid >> 2, lcw = (tid & 3) * 4;   // W: row lrw, k-cols [lcw, lcw+4)
    int mg = tid & 15, ng = tid >> 4;

    float4 xa = *reinterpret_cast<const float4*>(X + (size_t)(m0 + lrx) * EE + lcx);
    float4 xb = *reinterpret_cast<const float4*>(X + (size_t)(m0 + lrx) * EE + lcx + 4);
    float4 wa = *reinterpret_cast<const float4*>(W + (size_t)(f0 + lrw) * EE + lcw);

    unsigned long long acc[2][4] = {};

    for (int kt = 0; kt < EE; kt += 16) {
        __syncthreads();
        Xs[(lcx + 0) * 66 + lrx] = xa.x;
        Xs[(lcx + 1) * 66 + lrx] = xa.y;
        Xs[(lcx + 2) * 66 + lrx] = xa.z;
        Xs[(lcx + 3) * 66 + lrx] = xa.w;
        Xs[(lcx + 4) * 66 + lrx] = xb.x;
        Xs[(lcx + 5) * 66 + lrx] = xb.y;
        Xs[(lcx + 6) * 66 + lrx] = xb.z;
        Xs[(lcx + 7) * 66 + lrx] = xb.w;
        Ws[(lcw + 0) * 36 + lrw] = wa.x;
        Ws[(lcw + 1) * 36 + lrw] = wa.y;
        Ws[(lcw + 2) * 36 + lrw] = wa.z;
        Ws[(lcw + 3) * 36 + lrw] = wa.w;
        __syncthreads();
        if (kt + 16 < EE) {
            xa = *reinterpret_cast<const float4*>(X + (size_t)(m0 + lrx) * EE + kt + 16 + lcx);
            xb = *reinterpret_cast<const float4*>(X + (size_t)(m0 + lrx) * EE + kt + 16 + lcx + 4);
            wa = *reinterpret_cast<const float4*>(W + (size_t)(f0 + lrw) * EE + kt + 16 + lcw);
        }
#pragma unroll
        for (int k = 0; k < 16; k++) {
            unsigned long long a0 =
                *reinterpret_cast<const unsigned long long*>(&Xs[k * 66 + 2 * mg]);
            unsigned long long a1 =
                *reinterpret_cast<const unsigned long long*>(&Xs[k * 66 + 2 * mg + 32]);
#pragma unroll
            for (int nn = 0; nn < 4; nn++) {
                unsigned long long bv2 = dup2(Ws[k * 36 + ng * 4 + nn]);
                ffma2(acc[0][nn], a0, bv2);
                ffma2(acc[1][nn], a1, bv2);
            }
        }
    }

#pragma unroll
    for (int nn = 0; nn < 4; nn++) {
        int f = f0 + ng * 4 + nn;
        float bvv = bias[f];
#pragma unroll
        for (int mp = 0; mp < 2; mp++) {
            int m = m0 + 2 * mg + 32 * mp;     // even
            float v0 = lo32(acc[mp][nn]) + bvv;
            float v1 = hi32(acc[mp][nn]) + bvv;
            if (MODE == 0) {
                out[(size_t)m * EE + f] = v0;
                out[(size_t)(m + 1) * EE + f] = v1;
            } else {
                int b = m >> 4, s = m & 15, h = f >> 7, d = f & 127;
                size_t base = (((size_t)(b * HH + h)) * SS + s) * DD + d;
                out[base] = v0;
                out[base + DD] = v1;  // s+1, same b
            }
        }
    }
}

__global__ __launch_bounds__(128) void qkv_gemm(const float* __restrict__ emb,
                                                const float* __restrict__ Wq,
                                                const float* __restrict__ Wk,
                                                const float* __restrict__ Wv,
                                                const float* __restrict__ bq,
                                                const float* __restrict__ bk,
                                                const float* __restrict__ bv,
                                                float* __restrict__ kout,
                                                float* __restrict__ vout) {
    const float* W;
    const float* bias;
    float* o;
    if (blockIdx.z == 0) { W = Wq; bias = bq; o = g_q; }
    else if (blockIdx.z == 1) { W = Wk; bias = bk; o = kout; }
    else { W = Wv; bias = bv; o = vout; }
    gemm32_body<1>(emb, W, bias, o);
}

__global__ __launch_bounds__(128) void out_gemm(const float* __restrict__ Wo,
                                                const float* __restrict__ bo,
                                                float* __restrict__ out) {
    gemm32_body<0>(g_ctx, Wo, bo, out);
}

// =============================================================================
// Fused flash attention, one CTA per (b,h), 256 threads, 32-key tiles.
// Q in registers. Score partials staged through a plane aliasing the V region.
// Register-prefetched K/V. Fully parallel online softmax (8 warps x 2 rows).
// Compute loops are constant-trip (32 keys); the 16-key tail tile masks the
// stale upper half via the causal mask (P=0 there).
// =============================================================================
__global__ __launch_bounds__(256) void flash_kernel(const float* __restrict__ kc,
                                                    const float* __restrict__ vc,
                                                    const float* __restrict__ knew,
                                                    const float* __restrict__ vnew) {
    // SM[0:4224)    = Ks[j][132]
    // SM[4224:8448) = Vs[j][132]  (also SP[dg][16][33] between scores and reduce)
    // SM[0:8448)    = FB[256][33] for the final o reduction
    __shared__ __align__(16) float SM[8448];
    __shared__ float Ss[16 * 34];
    __shared__ float m_s[16], l_s[16], c_s[16];

    float* Ks = SM;
    float* Vs = SM + 4224;
    float* SP = SM + 4224;
    float* FB = SM;

    int tid = threadIdx.x;
    int bh = blockIdx.x;

    // --- stage-A (scores) ids ------------------------------------------------
    int qgA = tid & 3;          // 4 groups x 4 queries
    int kgA = (tid >> 2) & 7;   // keys j = kgA + 8*kk
    int dgA = tid >> 5;         // d in [dgA*16, dgA*16+16)

    // Q registers (tile-invariant)
    unsigned long long qreg[4][8];
    {
        const float* qb = g_q + (size_t)bh * (SS * DD);
#pragma unroll
        for (int qq = 0; qq < 4; qq++)
#pragma unroll
            for (int dp = 0; dp < 8; dp++)
                qreg[qq][dp] = *reinterpret_cast<const unsigned long long*>(
                    qb + (qgA * 4 + qq) * DD + dgA * 16 + 2 * dp);
    }

    // --- stage-C (PV) ids ----------------------------------------------------
    int dg2 = tid & 15;          // d-pairs: d = 2*dg2 + 32*r, r=0..3
    int qg2 = (tid >> 4) & 3;    // 4 groups x 4 queries
    int ksl = tid >> 6;          // 4 key slices x 8 keys
    unsigned long long o2[4][4] = {};  // [qq][r]

    // --- softmax ids ---------------------------------------------------------
    int lane = tid & 31;
    int srow = ((tid >> 5) << 1) + (lane >> 4);  // 0..15, one 16-lane group per row
    int sl = lane & 15;

    if (tid < 16) { m_s[tid] = -1e30f; l_s[tid] = 0.f; }

    // --- K/V tile loader ids -------------------------------------------------
    int jl = tid >> 3;           // row 0..31
    int cl = tid & 7;            // float4 cols cl, cl+8, cl+16, cl+24

    const float scale = 0.08838834764831845f;  // 1/sqrt(128)

    // preload tile 0 K
    float4 kpre[4], vpre[4];
    {
        const float* ks0 = kc + ((size_t)bh * TCACHE) * DD;
#pragma unroll
        for (int t = 0; t < 4; t++)
            kpre[t] = *reinterpret_cast<const float4*>(ks0 + (size_t)jl * DD + cl * 4 + 32 * t);
    }

    for (int tile = 0; tile < NTILES; tile++) {
        bool tail = (tile == 128);
        bool on = !tail || (jl < 16);

        // STS K (prefetched)
        if (on) {
#pragma unroll
            for (int t = 0; t < 4; t++)
                *reinterpret_cast<float4*>(&Ks[jl * 132 + cl * 4 + 32 * t]) = kpre[t];
        }
        __syncthreads();  // (a) K visible; all threads past previous PV

        // V prefetch for THIS tile (lands during scores)
        {
            const float* vsrc = !tail
                ? vc + ((size_t)bh * TCACHE + (size_t)tile * 32) * DD
                : vnew + (size_t)bh * (SS * DD);
            if (on) {
#pragma unroll
                for (int t = 0; t < 4; t++)
                    vpre[t] = *reinterpret_cast<const float4*>(
                        vsrc + (size_t)jl * DD + cl * 4 + 32 * t);
            }
        }

        // scores: acc[qq][kk] over this thread's 16 d's (always full 32 keys)
        {
            unsigned long long acc[4][4] = {};
#pragma unroll
            for (int dp = 0; dp < 8; dp++) {
#pragma unroll
                for (int kk = 0; kk < 4; kk++) {
                    unsigned long long kv =
                        *reinterpret_cast<const unsigned long long*>(
                            &Ks[(kgA + 8 * kk) * 132 + dgA * 16 + 2 * dp]);
#pragma unroll
                    for (int qq = 0; qq < 4; qq++)
                        ffma2(acc[qq][kk], qreg[qq][dp], kv);
                }
            }
#pragma unroll
            for (int qq = 0; qq < 4; qq++)
#pragma unroll
                for (int kk = 0; kk < 4; kk++)
                    SP[dgA * 528 + (qgA * 4 + qq) * 33 + (kgA + 8 * kk)] =
                        lo32(acc[qq][kk]) + hi32(acc[qq][kk]);
        }
        __syncthreads();  // (b) SP complete

        // reduce 8 d-partials -> Ss, scale, causal mask on tail
        {
#pragma unroll
            for (int half = 0; half < 2; half++) {
                int pp = tid + 256 * half;
                int q = pp >> 5, k = pp & 31;
                float s = 0.f;
#pragma unroll
                for (int dg = 0; dg < 8; dg++) s += SP[dg * 528 + q * 33 + k];
                s *= scale;
                if (tail && k > q) s = -1e30f;  // also kills k>=16 stale slots
                Ss[q * 34 + k] = s;
            }
        }
        __syncthreads();  // (c) Ss ready, SP consumed

        // STS V (over SP) + fully parallel online softmax
        if (on) {
#pragma unroll
            for (int t = 0; t < 4; t++)
                *reinterpret_cast<float4*>(&Vs[jl * 132 + cl * 4 + 32 * t]) = vpre[t];
        }
        {
            float s0 = Ss[srow * 34 + sl];
            float s1 = Ss[srow * 34 + sl + 16];
            float mx = fmaxf(s0, s1);
#pragma unroll
            for (int off = 8; off; off >>= 1)
                mx = fmaxf(mx, __shfl_xor_sync(0xffffffffu, mx, off));
            float mold = m_s[srow];
            float mnew = fmaxf(mold, mx);
            float p0 = __expf(s0 - mnew);
            float p1 = __expf(s1 - mnew);
            Ss[srow * 34 + sl] = p0;
            Ss[srow * 34 + sl + 16] = p1;
            float sum = p0 + p1;
#pragma unroll
            for (int off = 8; off; off >>= 1)
                sum += __shfl_xor_sync(0xffffffffu, sum, off);
            if (sl == 0) {
                float c = __expf(mold - mnew);
                m_s[srow] = mnew;
                l_s[srow] = l_s[srow] * c + sum;
                c_s[srow] = c;
            }
        }
        __syncthreads();  // (d) V + P + c ready

        // prefetch NEXT tile K (lands during PV)
        if (tile + 1 < NTILES) {
            int tn = tile + 1;
            const float* ksrc = (tn < 128)
                ? kc + ((size_t)bh * TCACHE + (size_t)tn * 32) * DD
                : knew + (size_t)bh * (SS * DD);
            if (tn < 128 || jl < 16) {
#pragma unroll
                for (int t = 0; t < 4; t++)
                    kpre[t] = *reinterpret_cast<const float4*>(
                        ksrc + (size_t)jl * DD + cl * 4 + 32 * t);
            }
        }

        // PV: o = o*c + P @ V on this thread's key slice (always 8 keys)
        {
            unsigned long long cf[4];
#pragma unroll
            for (int qq = 0; qq < 4; qq++) cf[qq] = dup2(c_s[qg2 * 4 + qq]);
#pragma unroll
            for (int qq = 0; qq < 4; qq++)
#pragma unroll
                for (int r = 0; r < 4; r++) fmul2(o2[qq][r], cf[qq]);

#pragma unroll
            for (int jj = 0; jj < 8; jj++) {
                int j = ksl * 8 + jj;
                unsigned long long pf[4];
#pragma unroll
                for (int qq = 0; qq < 4; qq++)
                    pf[qq] = dup2(Ss[(qg2 * 4 + qq) * 34 + j]);
#pragma unroll
                for (int r = 0; r < 4; r++) {
                    unsigned long long vv =
                        *reinterpret_cast<const unsigned long long*>(
                            &Vs[j * 132 + 2 * dg2 + 32 * r]);
#pragma unroll
                    for (int qq = 0; qq < 4; qq++) ffma2(o2[qq][r], pf[qq], vv);
                }
            }
        }
    }

    // final: reduce 4 key-slice partials through FB, normalize, write g_ctx
    __syncthreads();
    if (tid < 16) c_s[tid] = 1.f / l_s[tid];
#pragma unroll
    for (int qq = 0; qq < 4; qq++)
#pragma unroll
        for (int r = 0; r < 4; r++) {
            FB[tid * 33 + qq * 8 + r * 2]     = lo32(o2[qq][r]);
            FB[tid * 33 + qq * 8 + r * 2 + 1] = hi32(o2[qq][r]);
        }
    __syncthreads();
    if (tid < 64) {
        int b = bh >> 4, h = bh & 15;
#pragma unroll
        for (int i = 0; i < 32; i++) {
            float v = FB[tid * 33 + i] + FB[(tid + 64) * 33 + i] +
                      FB[(tid + 128) * 33 + i] + FB[(tid + 192) * 33 + i];
            int qq = i >> 3, r = (i >> 1) & 3, lh = i & 1;
            int q = qg2 * 4 + qq;
            int d = 2 * dg2 + 32 * r + lh;
            g_ctx[((size_t)(b * SS + q)) * EE + h * DD + d] = v * c_s[q];
        }
    }
}

// ---------------- launch -----------------------------------------------------
extern "C" void kernel_launch(void* const* d_in, const int* in_sizes, int n_in,
                              void* d_out, int out_size) {
    const float* emb = (const float*)d_in[0];
    const float* kc  = (const float*)d_in[1];
    const float* vc  = (const float*)d_in[2];
    const float* Wq  = (const float*)d_in[3];
    const float* bq  = (const float*)d_in[4];
    const float* Wk  = (const float*)d_in[5];
    const float* bk  = (const float*)d_in[6];
    const float* Wv  = (const float*)d_in[7];
    const float* bv  = (const float*)d_in[8];
    const float* Wo  = (const float*)d_in[9];
    const float* bo  = (const float*)d_in[10];

    float* out  = (float*)d_out;          // (8,16,2048)
    float* kout = out + MM * EE;          // k_new (8,16,16,128)
    float* vout = out + 2 * MM * EE;      // v_new (8,16,16,128)

    qkv_gemm<<<dim3(64, 2, 3), 128>>>(emb, Wq, Wk, Wv, bq, bk, bv, kout, vout);
    flash_kernel<<<128, 256>>>(kc, vc, kout, vout);
    out_gemm<<<dim3(64, 2, 1), 128>>>(Wo, bo, out);
}